// round 5
// baseline (speedup 1.0000x reference)
#include <cuda_runtime.h>
#include <math.h>

#define BS   64
#define CIN  256
#define II   1024
#define J    10
#define D    32
#define OD   320      // J*D
#define NTILE 8
#define TILE_I 128    // II / NTILE

typedef unsigned long long ull;

// ---------------- scratch (static device globals; no allocation) ----------------
__device__ float g_xsum [BS*CIN];            // sum_i x[b,c,i]
__device__ float g_u    [BS*J*CIN];          // accumulated u_j = W_j^T v_j
__device__ float g_vb   [BS*J];              // accumulated v_j . bias_j
__device__ float g_ypart[BS*NTILE*J*CIN];    // per-tile partial y
__device__ float g_cpart[BS*NTILE*J];        // per-tile partial sum_i c_ji

// ---------------- f32x2 helpers ----------------
static __device__ __forceinline__ void ffma2(ull &d, ull a, ull b) {
    asm("fma.rn.f32x2 %0, %1, %2, %0;" : "+l"(d) : "l"(a), "l"(b));
}
static __device__ __forceinline__ ull pack2(float lo, float hi) {
    ull r;
    asm("mov.b64 %0, {%1, %2};" : "=l"(r) : "f"(lo), "f"(hi));
    return r;
}
static __device__ __forceinline__ float lo2(ull v) {
    return __uint_as_float((unsigned int)(v & 0xffffffffu));
}
static __device__ __forceinline__ float hi2(ull v) {
    return __uint_as_float((unsigned int)(v >> 32));
}

// ---------------- K1: xsum[b,c] = sum_i x[b,c,i] ----------------
__global__ void k_xsum(const float* __restrict__ x) {
    int warp = (blockIdx.x * blockDim.x + threadIdx.x) >> 5;   // row id = b*CIN + c
    int lane = threadIdx.x & 31;
    if (warp >= BS * CIN) return;
    const float4* row = (const float4*)(x + (size_t)warp * II);
    float s = 0.0f;
    #pragma unroll
    for (int k = 0; k < II / 128; k++) {
        float4 v = row[k * 32 + lane];
        s += v.x + v.y + v.z + v.w;
    }
    #pragma unroll
    for (int off = 16; off; off >>= 1) s += __shfl_xor_sync(0xffffffffu, s, off);
    if (lane == 0) g_xsum[warp] = s;
}

// ---------------- K_sv: per (b,j): y-reduce -> s -> squash(v) -> u,vb | out ----
// grid (J, BS), 256 threads. mode: 0 iter1 (y=xsum/J, init u/vb),
// 1 middle (y from parts, accumulate u/vb), 2 final (write v to out)
__global__ void __launch_bounds__(256) k_sv(const float* __restrict__ W,
                                            const float* __restrict__ Wb,
                                            float* __restrict__ out, int mode) {
    int j = blockIdx.x, b = blockIdx.y, t = threadIdx.x;
    int wid = t >> 5, lane = t & 31;
    __shared__ __align__(16) float ysm[CIN];
    __shared__ __align__(16) float wsm[D * CIN];   // cached W_j tile (32KB)
    __shared__ float ssm[D];
    __shared__ float vsm[D];
    __shared__ float csum_s;

    // ---- y[c] for this (b,j) ----
    float yv;
    if (mode == 0) {
        yv = g_xsum[b * CIN + t] * (1.0f / (float)J);
        if (t == 0) csum_s = (float)II / (float)J;
    } else {
        yv = 0.0f;
        #pragma unroll
        for (int p = 0; p < NTILE; p++)
            yv += g_ypart[((b * NTILE + p) * J + j) * CIN + t];
        if (t == 0) {
            float a = 0.0f;
            #pragma unroll
            for (int p = 0; p < NTILE; p++) a += g_cpart[(b * NTILE + p) * J + j];
            csum_s = a;
        }
    }
    ysm[t] = yv;
    __syncthreads();
    float csum = csum_s;

    // ---- s[d] = W[jD+d,:].y + csum*Wb[jD+d]; also stash W_j in smem ----
    #pragma unroll
    for (int d = wid; d < D; d += 8) {
        const float4* wr = (const float4*)(W + (size_t)(j * D + d) * CIN);
        float4 w0 = wr[lane * 2], w1 = wr[lane * 2 + 1];
        ((float4*)(wsm + d * CIN))[lane * 2]     = w0;
        ((float4*)(wsm + d * CIN))[lane * 2 + 1] = w1;
        const float4* yr = (const float4*)ysm;
        float4 y0 = yr[lane * 2], y1 = yr[lane * 2 + 1];
        float a = w0.x * y0.x + w0.y * y0.y + w0.z * y0.z + w0.w * y0.w
                + w1.x * y1.x + w1.y * y1.y + w1.z * y1.z + w1.w * y1.w;
        #pragma unroll
        for (int off = 16; off; off >>= 1) a += __shfl_xor_sync(0xffffffffu, a, off);
        if (lane == 0) ssm[d] = a + csum * Wb[j * D + d];
    }
    __syncthreads();

    // ---- squash + v (warp 0) ----
    if (wid == 0) {
        float s = ssm[lane];
        float ns = s * s;
        #pragma unroll
        for (int off = 16; off; off >>= 1) ns += __shfl_xor_sync(0xffffffffu, ns, off);
        float coef = ns / ((1.0f + ns) * sqrtf(ns));
        float v = s * coef;
        vsm[lane] = v;
        if (mode == 2) {
            out[(b * J + j) * D + lane] = v;
        } else {
            float pv = v * Wb[j * D + lane];
            #pragma unroll
            for (int off = 16; off; off >>= 1) pv += __shfl_xor_sync(0xffffffffu, pv, off);
            if (lane == 0) g_vb[b * J + j] = (mode == 0) ? pv : g_vb[b * J + j] + pv;
        }
    }
    __syncthreads();

    // ---- u[c] = sum_d v[d] * W_j[d, c] from smem ----
    if (mode != 2) {
        float a = 0.0f;
        #pragma unroll
        for (int d = 0; d < D; d++)
            a = fmaf(vsm[d], wsm[d * CIN + t], a);
        int idx = (b * J + j) * CIN + t;
        g_u[idx] = (mode == 0) ? a : g_u[idx] + a;
    }
}

// ---------------- K_pass: logits -> softmax -> partial y, csum ----------------
// grid (NTILE, BS), 128 threads. phase A: thread owns one i. phase B: thread owns
// one c within each 128-channel half; x staged per half in swizzled smem chunks.
__global__ void __launch_bounds__(128) k_pass(const float* __restrict__ x) {
    __shared__ __align__(16) ull   usm[J * (CIN / 2)];     // u packed in c-pairs, 10KB
    __shared__ float vbs[J];
    __shared__ __align__(16) float cssm[J * TILE_I];       // softmax coeffs [j][i], 5KB
    __shared__ __align__(16) float xsm[128 * 32];          // half-channel 32-i chunk, 16KB

    int b = blockIdx.y, tile = blockIdx.x, t = threadIdx.x;
    int wid = t >> 5, lane = t & 31;

    const ull* up = (const ull*)(g_u + (size_t)b * J * CIN);
    for (int idx = t; idx < J * CIN / 2; idx += 128) usm[idx] = up[idx];
    if (t < J) vbs[t] = g_vb[b * J + t];
    __syncthreads();

    const float* xb = x + (size_t)b * CIN * II;
    int i0 = tile * TILE_I;

    // ---- phase A: logit[j] = u_j . x[:, i] + vb_j ; i = i0 + t ----
    {
        const float* xi = xb + i0 + t;
        ull acc[J];
        #pragma unroll
        for (int j = 0; j < J; j++) acc[j] = 0ull;
        #pragma unroll 4
        for (int cq = 0; cq < CIN / 4; cq++) {
            float x0 = __ldg(xi + (size_t)(4 * cq + 0) * II);
            float x1 = __ldg(xi + (size_t)(4 * cq + 1) * II);
            float x2 = __ldg(xi + (size_t)(4 * cq + 2) * II);
            float x3 = __ldg(xi + (size_t)(4 * cq + 3) * II);
            ull x01 = pack2(x0, x1), x23 = pack2(x2, x3);
            #pragma unroll
            for (int j = 0; j < J; j++) {
                ulonglong2 u4 = *(const ulonglong2*)(usm + j * (CIN / 2) + cq * 2);
                ffma2(acc[j], u4.x, x01);
                ffma2(acc[j], u4.y, x23);
            }
        }
        float lg[J];
        #pragma unroll
        for (int j = 0; j < J; j++) lg[j] = lo2(acc[j]) + hi2(acc[j]) + vbs[j];
        float m = lg[0];
        #pragma unroll
        for (int j = 1; j < J; j++) m = fmaxf(m, lg[j]);
        float s = 0.0f;
        #pragma unroll
        for (int j = 0; j < J; j++) { lg[j] = __expf(lg[j] - m); s += lg[j]; }
        float r = 1.0f / s;
        #pragma unroll
        for (int j = 0; j < J; j++) cssm[j * TILE_I + t] = lg[j] * r;
    }
    __syncthreads();

    // ---- csum partials (warp-strided over j, lanes over 128 i) ----
    for (int j = wid; j < J; j += 4) {
        float4 a = ((const float4*)(cssm + j * TILE_I))[lane];
        float sc = a.x + a.y + a.z + a.w;
        #pragma unroll
        for (int off = 16; off; off >>= 1) sc += __shfl_xor_sync(0xffffffffu, sc, off);
        if (lane == 0) g_cpart[(b * NTILE + tile) * J + j] = sc;
    }

    // ---- phase B: y[j][c] = sum_i c[j,i] * x[c,i], c-halves x i-chunks ----
    #pragma unroll 1
    for (int cc = 0; cc < 2; cc++) {
        ull yacc[J][2];
        #pragma unroll
        for (int j = 0; j < J; j++) { yacc[j][0] = 0ull; yacc[j][1] = 0ull; }

        #pragma unroll 1
        for (int ch = 0; ch < TILE_I / 32; ch++) {
            __syncthreads();  // previous chunk fully consumed
            // stage x[cc*128 + 0..127][ch*32 + 0..31] coalesced + swizzled
            #pragma unroll
            for (int sw = 0; sw < 8; sw++) {
                int row = sw * 16 + (t >> 3);
                int q   = t & 7;
                float4 v = *(const float4*)(xb + (size_t)(cc * 128 + row) * II
                                            + i0 + ch * 32 + q * 4);
                int sidx = row * 32 + ((q ^ (row & 7)) << 2);
                *(float4*)(xsm + sidx) = v;
            }
            __syncthreads();
            // accumulate: thread t = local channel t
            #pragma unroll
            for (int g = 0; g < 8; g++) {          // 4 i per group
                int sidx = t * 32 + ((g ^ (t & 7)) << 2);
                float4 xv = *(const float4*)(xsm + sidx);
                ull x01 = pack2(xv.x, xv.y), x23 = pack2(xv.z, xv.w);
                int ii = ch * 32 + g * 4;
                #pragma unroll
                for (int j = 0; j < J; j++) {
                    float4 cv = *(const float4*)(cssm + j * TILE_I + ii);  // uniform
                    ffma2(yacc[j][0], pack2(cv.x, cv.y), x01);
                    ffma2(yacc[j][1], pack2(cv.z, cv.w), x23);
                }
            }
        }
        #pragma unroll
        for (int j = 0; j < J; j++)
            g_ypart[((b * NTILE + tile) * J + j) * CIN + cc * 128 + t] =
                (lo2(yacc[j][0]) + hi2(yacc[j][0])) + (lo2(yacc[j][1]) + hi2(yacc[j][1]));
    }
}

// ---------------- launch ----------------
extern "C" void kernel_launch(void* const* d_in, const int* in_sizes, int n_in,
                              void* d_out, int out_size) {
    const float* x  = (const float*)d_in[0];   // [64,256,32,32]
    const float* W  = (const float*)d_in[1];   // [320,256]
    const float* Wb = (const float*)d_in[2];   // [320]
    float* out = (float*)d_out;                // [64,10,32]

    k_xsum<<<BS * CIN / 8, 256>>>(x);
    k_sv  <<<dim3(J, BS), 256>>>(W, Wb, out, 0);   // iter1: v1, u1, vb1
    k_pass<<<dim3(NTILE, BS), 128>>>(x);           // iter2 logits+softmax+y
    k_sv  <<<dim3(J, BS), 256>>>(W, Wb, out, 1);   // iter2: v2, u+=, vb+=
    k_pass<<<dim3(NTILE, BS), 128>>>(x);           // iter3 logits+softmax+y
    k_sv  <<<dim3(J, BS), 256>>>(W, Wb, out, 2);   // iter3: v3 -> out
}

// round 6
// speedup vs baseline: 1.0261x; 1.0261x over previous
#include <cuda_runtime.h>
#include <math.h>

#define BS   64
#define CIN  256
#define II   1024
#define J    10
#define D    32
#define NTILE 4
#define TILE_I 256   // II / NTILE

typedef unsigned long long ull;

// ---------------- scratch (static device globals; no allocation) ----------------
__device__ float g_xsum [BS*CIN];
__device__ float g_u    [BS*J*CIN];          // u_j = W_j^T v_j per batch
__device__ float g_vb   [BS*J];
__device__ float g_ypart[BS*NTILE*J*CIN];
__device__ float g_cpart[BS*NTILE*J];

// ---------------- f32x2 helpers ----------------
static __device__ __forceinline__ void ffma2(ull &d, ull a, ull b) {
    asm("fma.rn.f32x2 %0, %1, %2, %0;" : "+l"(d) : "l"(a), "l"(b));
}
static __device__ __forceinline__ ull pack2(float lo, float hi) {
    ull r;
    asm("mov.b64 %0, {%1, %2};" : "=l"(r) : "f"(lo), "f"(hi));
    return r;
}
static __device__ __forceinline__ ull dup2(float x) {
    unsigned int u = __float_as_uint(x);
    return ((ull)u << 32) | (ull)u;
}
static __device__ __forceinline__ float lo2(ull v) {
    return __uint_as_float((unsigned int)(v & 0xffffffffu));
}
static __device__ __forceinline__ float hi2(ull v) {
    return __uint_as_float((unsigned int)(v >> 32));
}

// ---------------- K1: xsum[b,c] = sum_i x[b,c,i] ----------------
__global__ void k_xsum(const float* __restrict__ x) {
    int warp = (blockIdx.x * blockDim.x + threadIdx.x) >> 5;   // row = b*CIN + c
    int lane = threadIdx.x & 31;
    if (warp >= BS * CIN) return;
    const float4* row = (const float4*)(x + (size_t)warp * II);
    float s = 0.0f;
    #pragma unroll
    for (int k = 0; k < II / 128; k++) {
        float4 v = row[k * 32 + lane];
        s += v.x + v.y + v.z + v.w;
    }
    #pragma unroll
    for (int off = 16; off; off >>= 1) s += __shfl_xor_sync(0xffffffffu, s, off);
    if (lane == 0) g_xsum[warp] = s;
}

// ---------------- K_sv2: W-stationary, 4 batches per block ----------------
// grid (J, BS/4), 256 threads. mode: 0 iter1 (y=xsum/J, init u/vb),
// 1 middle (accumulate u/vb), 2 final (write v to out)
__global__ void __launch_bounds__(256) k_sv2(const float* __restrict__ W,
                                             const float* __restrict__ Wb,
                                             float* __restrict__ out, int mode) {
    int j = blockIdx.x, b0 = blockIdx.y * 4, t = threadIdx.x;
    __shared__ float  wsmT[CIN * 33];    // W_j transposed, padded: [c*33 + d]
    __shared__ float  ysm [4 * CIN];
    __shared__ float4 vsm4[D];           // vsm4[d] = v for the 4 batches
    __shared__ float  csum_s[4];

    // load W_j once, transposed (coalesced LDG; STS bank (c+d)%32 conflict-free)
    #pragma unroll
    for (int d = 0; d < D; d++)
        wsmT[t * 33 + d] = W[(size_t)(j * D + d) * CIN + t];

    // y[bb][c]
    if (mode == 0) {
        #pragma unroll
        for (int bb = 0; bb < 4; bb++)
            ysm[bb * CIN + t] = g_xsum[(b0 + bb) * CIN + t] * (1.0f / (float)J);
        if (t < 4) csum_s[t] = (float)II / (float)J;
    } else {
        #pragma unroll
        for (int bb = 0; bb < 4; bb++) {
            float a = 0.0f;
            #pragma unroll
            for (int p = 0; p < NTILE; p++)
                a += g_ypart[(((size_t)(b0 + bb) * NTILE + p) * J + j) * CIN + t];
            ysm[bb * CIN + t] = a;
        }
        if (t < 4) {
            float a = 0.0f;
            #pragma unroll
            for (int p = 0; p < NTILE; p++)
                a += g_cpart[((b0 + t) * NTILE + p) * J + j];
            csum_s[t] = a;
        }
    }
    __syncthreads();

    // s, squash, v: threads 0..127, bb = t>>5 (warp per batch), d = t&31
    if (t < 128) {
        int bb = t >> 5, d = t & 31;
        const float* yr = ysm + bb * CIN;
        float a0 = 0.f, a1 = 0.f, a2 = 0.f, a3 = 0.f;
        #pragma unroll 8
        for (int c = 0; c < CIN; c += 4) {
            a0 = fmaf(wsmT[(c    ) * 33 + d], yr[c    ], a0);
            a1 = fmaf(wsmT[(c + 1) * 33 + d], yr[c + 1], a1);
            a2 = fmaf(wsmT[(c + 2) * 33 + d], yr[c + 2], a2);
            a3 = fmaf(wsmT[(c + 3) * 33 + d], yr[c + 3], a3);
        }
        float s = (a0 + a1) + (a2 + a3) + csum_s[bb] * Wb[j * D + d];
        float ns = s * s;
        #pragma unroll
        for (int off = 16; off; off >>= 1) ns += __shfl_xor_sync(0xffffffffu, ns, off);
        float coef = ns / ((1.0f + ns) * sqrtf(ns));
        float v = s * coef;
        ((float*)vsm4)[d * 4 + bb] = v;
        if (mode == 2) {
            out[((b0 + bb) * J + j) * D + d] = v;
        } else {
            float pv = v * Wb[j * D + d];
            #pragma unroll
            for (int off = 16; off; off >>= 1) pv += __shfl_xor_sync(0xffffffffu, pv, off);
            if (d == 0) {
                int gi = (b0 + bb) * J + j;
                g_vb[gi] = (mode == 0) ? pv : g_vb[gi] + pv;
            }
        }
    }
    __syncthreads();

    // u[bb][c] = sum_d v[bb][d] * W_j[d][c]; thread = c, W from smem (no re-read)
    if (mode != 2) {
        float u0 = 0.f, u1 = 0.f, u2 = 0.f, u3 = 0.f;
        #pragma unroll
        for (int d = 0; d < D; d++) {
            float  w  = wsmT[t * 33 + d];   // bank (t+d)%32: conflict-free
            float4 v4 = vsm4[d];            // broadcast
            u0 = fmaf(w, v4.x, u0); u1 = fmaf(w, v4.y, u1);
            u2 = fmaf(w, v4.z, u2); u3 = fmaf(w, v4.w, u3);
        }
        float uu[4] = {u0, u1, u2, u3};
        #pragma unroll
        for (int bb = 0; bb < 4; bb++) {
            size_t idx = ((size_t)(b0 + bb) * J + j) * CIN + t;
            g_u[idx] = (mode == 0) ? uu[bb] : g_u[idx] + uu[bb];
        }
    }
}

// ---------------- K_pass: logits -> softmax -> partial y, csum ----------------
// grid (NTILE, BS), 256 threads.
// smem region1 (20480B) is time-multiplexed: usm (phase A) -> psm (combine) -> xsm (phase B)
__global__ void __launch_bounds__(256) k_pass(const float* __restrict__ x) {
    __shared__ __align__(16) char  sm1[20480];
    __shared__ __align__(16) float cssm[J * TILE_I];   // 10240B
    __shared__ float vbs[J];

    int b = blockIdx.y, tile = blockIdx.x, t = threadIdx.x;
    int wid = t >> 5, lane = t & 31;

    ull*   usm = (ull*)sm1;      // [j*CIN + c], u dup-packed
    ull*   psm = (ull*)sm1;      // [q*J + j], cg=1 partial logits (aliased)
    float* xsm = (float*)sm1;    // [row*20 + i], staged x chunk (aliased)

    const float* gu = g_u + (size_t)b * J * CIN;
    #pragma unroll
    for (int k = 0; k < 10; k++) {
        int idx = k * 256 + t;
        usm[idx] = dup2(gu[idx]);
    }
    if (t < J) vbs[t] = g_vb[b * J + t];
    __syncthreads();

    const float* xb = x + (size_t)b * CIN * II;
    int i0 = tile * TILE_I;

    // ---- phase A: thread (cg = t>>7, q = t&127) handles i-pair (2q, 2q+1),
    //      channels [cg*128, cg*128+128) ----
    int q = t & 127, cg = t >> 7;
    ull a[J];
    #pragma unroll
    for (int j = 0; j < J; j++) a[j] = 0ull;
    {
        const float* xg = xb + (size_t)cg * 128 * II + i0 + 2 * q;
        #pragma unroll 2
        for (int cc = 0; cc < 64; cc++) {
            ull xa  = *(const ull*)(xg + (size_t)(2 * cc    ) * II);
            ull xb2 = *(const ull*)(xg + (size_t)(2 * cc + 1) * II);
            const ull* up = usm + cg * 128 + cc * 2;
            #pragma unroll
            for (int j = 0; j < J; j++) {
                ulonglong2 ud = *(const ulonglong2*)(up + j * CIN);
                ffma2(a[j], ud.x, xa);
                ffma2(a[j], ud.y, xb2);
            }
        }
    }
    __syncthreads();             // all usm reads complete before psm overwrite
    if (cg == 1) {
        #pragma unroll
        for (int j = 0; j < J; j++) psm[q * J + j] = a[j];
    }
    __syncthreads();
    if (cg == 0) {
        float lg0[J], lg1[J];
        #pragma unroll
        for (int j = 0; j < J; j++) {
            ull p = psm[q * J + j];
            lg0[j] = lo2(a[j]) + lo2(p) + vbs[j];
            lg1[j] = hi2(a[j]) + hi2(p) + vbs[j];
        }
        float m0 = lg0[0], m1 = lg1[0];
        #pragma unroll
        for (int j = 1; j < J; j++) { m0 = fmaxf(m0, lg0[j]); m1 = fmaxf(m1, lg1[j]); }
        float s0 = 0.f, s1 = 0.f;
        #pragma unroll
        for (int j = 0; j < J; j++) {
            lg0[j] = __expf(lg0[j] - m0); s0 += lg0[j];
            lg1[j] = __expf(lg1[j] - m1); s1 += lg1[j];
        }
        float r0 = 1.0f / s0, r1 = 1.0f / s1;
        #pragma unroll
        for (int j = 0; j < J; j++)
            *(ull*)(cssm + j * TILE_I + 2 * q) = pack2(lg0[j] * r0, lg1[j] * r1);
    }
    __syncthreads();

    // ---- csum partials ----
    for (int j = wid; j < J; j += 8) {
        const float4* p = (const float4*)(cssm + j * TILE_I);
        float4 a1 = p[lane * 2], b4 = p[lane * 2 + 1];
        float sc = a1.x + a1.y + a1.z + a1.w + b4.x + b4.y + b4.z + b4.w;
        #pragma unroll
        for (int off = 16; off; off >>= 1) sc += __shfl_xor_sync(0xffffffffu, sc, off);
        if (lane == 0) g_cpart[(b * NTILE + tile) * J + j] = sc;
    }

    // ---- phase B: y[j][c=t] = sum_i c[j,i]*x[c,i]; 16-i chunks staged in xsm ----
    ull yacc[J][2];
    #pragma unroll
    for (int j = 0; j < J; j++) { yacc[j][0] = 0ull; yacc[j][1] = 0ull; }

    int srow = t >> 2, sq = t & 3;
    #pragma unroll 1
    for (int ch = 0; ch < TILE_I / 16; ch++) {
        __syncthreads();   // prev chunk consumed (first iter: psm/cssm settled)
        #pragma unroll
        for (int s = 0; s < 4; s++) {
            int row = s * 64 + srow;
            float4 v = *(const float4*)(xb + (size_t)row * II + i0 + ch * 16 + sq * 4);
            *(float4*)(xsm + row * 20 + sq * 4) = v;
        }
        __syncthreads();
        #pragma unroll
        for (int g = 0; g < 4; g++) {
            ulonglong2 xv = *(const ulonglong2*)(xsm + t * 20 + g * 4);
            int ii = ch * 16 + g * 4;
            #pragma unroll
            for (int j = 0; j < J; j++) {
                ulonglong2 cv = *(const ulonglong2*)(cssm + j * TILE_I + ii);
                ffma2(yacc[j][0], cv.x, xv.x);
                ffma2(yacc[j][1], cv.y, xv.y);
            }
        }
    }
    #pragma unroll
    for (int j = 0; j < J; j++)
        g_ypart[(((size_t)b * NTILE + tile) * J + j) * CIN + t] =
            (lo2(yacc[j][0]) + hi2(yacc[j][0])) + (lo2(yacc[j][1]) + hi2(yacc[j][1]));
}

// ---------------- launch ----------------
extern "C" void kernel_launch(void* const* d_in, const int* in_sizes, int n_in,
                              void* d_out, int out_size) {
    const float* x  = (const float*)d_in[0];   // [64,256,32,32]
    const float* W  = (const float*)d_in[1];   // [320,256]
    const float* Wb = (const float*)d_in[2];   // [320]
    float* out = (float*)d_out;                // [64,10,32]

    k_xsum<<<BS * CIN / 8, 256>>>(x);
    k_sv2 <<<dim3(J, BS / 4), 256>>>(W, Wb, out, 0);  // iter1: v1, u1, vb1
    k_pass<<<dim3(NTILE, BS), 256>>>(x);              // iter2 logits+softmax+y
    k_sv2 <<<dim3(J, BS / 4), 256>>>(W, Wb, out, 1);  // iter2: v2, u+=, vb+=
    k_pass<<<dim3(NTILE, BS), 256>>>(x);              // iter3 logits+softmax+y
    k_sv2 <<<dim3(J, BS / 4), 256>>>(W, Wb, out, 2);  // iter3: v3 -> out
}